// round 1
// baseline (speedup 1.0000x reference)
#include <cuda_runtime.h>
#include <float.h>

// ---------------- problem constants ----------------
#define B_   16
#define S_   512
#define D_   768
#define H_   12
#define HD_  64
#define K_   16
#define NS_  128
#define R_   32
#define BS_  (B_*S_)          // 8192 rows
#define SC_  (B_*H_*S_*S_)    // scores elements

// ---------------- scratch (__device__ globals; no allocs allowed) ----------------
__device__ float    g_xnorm[BS_];
__device__ float    g_sbuf[B_*NS_*D_];
__device__ float    g_dist[B_*S_*NS_];
__device__ double   g_sum[B_], g_sumsq[B_];
__device__ unsigned g_minb[B_], g_maxb[B_];
__device__ float    g_topo[B_*D_];
__device__ float    g_qkv[BS_*3*D_];
__device__ float    g_scores[SC_];
__device__ float    g_attnO[BS_*D_];
__device__ float    g_attnP[BS_*D_];
__device__ float    g_x1[BS_*D_];
__device__ float    g_ffnh[BS_*2*D_];
__device__ float    g_ffn2[BS_*D_];

// ---------------- generic tiled SGEMM ----------------
// C[M,N] = A[M,K] @ B (NN: B=[K,N], NT: B=[N,K]) with batched z-offsets and epilogues.
// EPI: 0 = +bias (bias may be null), 1 = gelu(exact)(x+bias), 2 = *alpha, 3 = cdist sqrt.
template<int BM,int BN,int BK,int TM,int TN,bool BNT,int EPI>
__global__ __launch_bounds__((BM/TM)*(BN/TN))
void gemm_k(const float* __restrict__ A, const float* __restrict__ Bp,
            float* __restrict__ C, const float* __restrict__ bias,
            int M, int N, int Kd, int lda, int ldb, int ldc,
            int Hdiv, long sAb, long sAh, long sBb, long sBh, long sCb, long sCh,
            float alpha, const float* __restrict__ xnorm, const int* __restrict__ sidx)
{
    constexpr int THREADS = (BM/TM)*(BN/TN);
    __shared__ float As[BK][BM];
    __shared__ float Bs[BK][BN];

    const int z  = blockIdx.z;
    const int zb = z / Hdiv, zh = z - zb*Hdiv;
    A  += zb*sAb + zh*sAh;
    Bp += zb*sBb + zh*sBh;
    C  += zb*sCb + zh*sCh;
    const float* xn = (EPI==3) ? (xnorm + (long)z*M) : xnorm;

    const int n0 = blockIdx.x * BN;
    const int m0 = blockIdx.y * BM;
    const int tid = threadIdx.x;
    const int tx = tid % (BN/TN);
    const int ty = tid / (BN/TN);

    float acc[TM][TN];
#pragma unroll
    for (int i=0;i<TM;i++)
#pragma unroll
        for (int j=0;j<TN;j++) acc[i][j]=0.f;

    constexpr int A4 = BM*BK/4;
    constexpr int B4 = BN*BK/4;

    for (int k0=0; k0<Kd; k0+=BK) {
        // load A tile (transpose to As[k][m])
#pragma unroll
        for (int i=tid; i<A4; i+=THREADS) {
            int r  = i / (BK/4);
            int c4 = (i % (BK/4))*4;
            float4 v = *(const float4*)(A + (long)(m0+r)*lda + k0 + c4);
            As[c4+0][r]=v.x; As[c4+1][r]=v.y; As[c4+2][r]=v.z; As[c4+3][r]=v.w;
        }
        if (BNT) {
#pragma unroll
            for (int i=tid; i<B4; i+=THREADS) {
                int r  = i / (BK/4);
                int c4 = (i % (BK/4))*4;
                float4 v = *(const float4*)(Bp + (long)(n0+r)*ldb + k0 + c4);
                Bs[c4+0][r]=v.x; Bs[c4+1][r]=v.y; Bs[c4+2][r]=v.z; Bs[c4+3][r]=v.w;
            }
        } else {
#pragma unroll
            for (int i=tid; i<B4; i+=THREADS) {
                int r  = i / (BN/4);
                int c4 = (i % (BN/4))*4;
                float4 v = *(const float4*)(Bp + (long)(k0+r)*ldb + n0 + c4);
                *(float4*)&Bs[r][c4] = v;
            }
        }
        __syncthreads();
#pragma unroll
        for (int kk=0; kk<BK; kk++) {
            float ar[TM], br[TN];
#pragma unroll
            for (int i=0;i<TM;i+=4) *(float4*)&ar[i] = *(const float4*)&As[kk][ty*TM+i];
#pragma unroll
            for (int j=0;j<TN;j+=4) *(float4*)&br[j] = *(const float4*)&Bs[kk][tx*TN+j];
#pragma unroll
            for (int i=0;i<TM;i++)
#pragma unroll
                for (int j=0;j<TN;j++) acc[i][j] = fmaf(ar[i], br[j], acc[i][j]);
        }
        __syncthreads();
    }

    // epilogue (vectorized stores; all dims/offsets are multiples of 4)
#pragma unroll
    for (int i=0;i<TM;i++) {
        int gm = m0 + ty*TM + i;
#pragma unroll
        for (int j4=0;j4<TN;j4+=4) {
            int gn = n0 + tx*TN + j4;
            float4 v;
            float* vp = &v.x;
#pragma unroll
            for (int u=0;u<4;u++) {
                float a = acc[i][j4+u];
                if (EPI==0) {
                    if (bias) a += bias[gn+u];
                } else if (EPI==1) {
                    float t = a + bias[gn+u];
                    a = t * normcdff(t);            // exact GELU
                } else if (EPI==2) {
                    a *= alpha;
                } else if (EPI==3) {
                    float nx = xn[gm];
                    float ns = xn[sidx[gn+u]];
                    a = sqrtf(fmaxf(nx + ns - 2.f*a, 0.f));
                }
                vp[u] = a;
            }
            *(float4*)(C + (long)gm*ldc + gn) = v;
        }
    }
}

// ---------------- block reduce helper (256 threads) ----------------
__device__ __forceinline__ float blockReduceSum256(float v, float* red) {
#pragma unroll
    for (int o=16;o;o>>=1) v += __shfl_xor_sync(0xffffffffu, v, o);
    int w = threadIdx.x>>5, l = threadIdx.x&31;
    if (l==0) red[w] = v;
    __syncthreads();
    float r = (threadIdx.x < 8) ? red[threadIdx.x] : 0.f;
    if (w==0) {
#pragma unroll
        for (int o=4;o;o>>=1) r += __shfl_xor_sync(0xffffffffu, r, o);
        if (l==0) red[0] = r;
    }
    __syncthreads();
    float out = red[0];
    __syncthreads();
    return out;
}

// ---------------- small kernels ----------------
__global__ void init_k() {
    int t = threadIdx.x;
    if (t < B_) { g_sum[t]=0.0; g_sumsq[t]=0.0; g_minb[t]=0x7f7fffffu; g_maxb[t]=0u; }
}

__global__ void xnorm_k(const float* __restrict__ x) {
    __shared__ float red[8];
    long r = blockIdx.x; int tid = threadIdx.x;
    float loc = 0.f;
    for (int d=tid; d<D_; d+=256) { float t = x[r*D_+d]; loc += t*t; }
    float s = blockReduceSum256(loc, red);
    if (tid==0) g_xnorm[r] = s;
}

__global__ void gather_k(const float* __restrict__ x, const int* __restrict__ sidx) {
    int j = blockIdx.x, b = blockIdx.y;
    int s = sidx[j];
    const float4* src = (const float4*)(x + ((long)b*S_ + s)*D_);
    float4* dst = (float4*)(g_sbuf + ((long)b*NS_ + j)*D_);
    dst[threadIdx.x] = src[threadIdx.x];   // 192 threads * float4 = 768 floats
}

// one warp per (b,s) row of 128 distances; extract 16 smallest iteratively
__global__ void topk_stats_k() {
    int warp = threadIdx.x >> 5, lane = threadIdx.x & 31;
    long row = (long)blockIdx.x*8 + warp;          // 8192 rows total
    const float4* p = (const float4*)(g_dist + row*NS_);
    float4 v4 = p[lane];
    float v[4] = {v4.x, v4.y, v4.z, v4.w};
    float lsum=0.f, lsq=0.f, mn0=0.f, mx15=0.f;
#pragma unroll
    for (int it=0; it<K_; ++it) {
        float lv = fminf(fminf(v[0],v[1]), fminf(v[2],v[3]));
        float m = lv;
#pragma unroll
        for (int o=16;o;o>>=1) m = fminf(m, __shfl_xor_sync(0xffffffffu, m, o));
        unsigned bal = __ballot_sync(0xffffffffu, lv==m);
        int src = __ffs(bal)-1;
        if (lane==src) {
            if      (v[0]==m) v[0]=FLT_MAX;
            else if (v[1]==m) v[1]=FLT_MAX;
            else if (v[2]==m) v[2]=FLT_MAX;
            else              v[3]=FLT_MAX;
        }
        lsum += m; lsq += m*m;
        if (it==0) mn0 = m;
        mx15 = m;
    }
    if (lane==0) {
        int b = (int)(row >> 9);
        atomicAdd(&g_sum[b],   (double)lsum);
        atomicAdd(&g_sumsq[b], (double)lsq);
        atomicMin(&g_minb[b], __float_as_uint(mn0));
        atomicMax(&g_maxb[b], __float_as_uint(mx15));
    }
}

// stats -> landscape MLP -> gated topo embedding, one block per batch
__global__ void mlp_topo_k(const float* __restrict__ w1, const float* __restrict__ b1,
                           const float* __restrict__ w2, const float* __restrict__ b2,
                           const float* __restrict__ wd0, const float* __restrict__ bd0,
                           const float* __restrict__ topo_w, const float* __restrict__ topo_b,
                           const float* __restrict__ gate) {
    int b = blockIdx.x, tid = threadIdx.x;
    __shared__ float st[6], h1[192], h2[R_], land[R_];
    if (tid==0) {
        double n = 8192.0;
        double s = g_sum[b], sq = g_sumsq[b];
        double mean = s / n;
        double var  = (sq - s*s/n) / (n - 1.0);    // unbiased (torch.std)
        float  sd   = sqrtf(fmaxf((float)var, 0.f));
        st[0]=(float)mean; st[1]=sd;
        st[2]=__uint_as_float(g_minb[b]); st[3]=__uint_as_float(g_maxb[b]);
        st[4]=(float)mean*0.5f; st[5]=sd*0.5f;
    }
    __syncthreads();
    if (tid < 192) {
        float a = b1[tid];
#pragma unroll
        for (int i=0;i<6;i++) a += st[i]*w1[i*192+tid];
        h1[tid] = fmaxf(a, 0.f);
    }
    __syncthreads();
    if (tid < R_) {
        float a = b2[tid];
        for (int i=0;i<192;i++) a += h1[i]*w2[i*R_+tid];
        h2[tid] = a;
    }
    __syncthreads();
    if (tid < R_) {
        float a = bd0[tid];
#pragma unroll
        for (int i=0;i<R_;i++) a += h2[i]*wd0[i*R_+tid];
        land[tid] = a;
    }
    __syncthreads();
    float gt = *gate;
    for (int d=tid; d<D_; d+=blockDim.x) {
        float a = topo_b[d];
#pragma unroll
        for (int i=0;i<R_;i++) a += land[i]*topo_w[i*D_+d];
        g_topo[b*D_+d] = gt*a;
    }
}

// softmax over rows of 512, in place; one block (128 thr) per row
__global__ void softmax_k() {
    long r = blockIdx.x;
    float4* p4 = (float4*)(g_scores + r*(long)S_);
    int tid = threadIdx.x, w = tid>>5, l = tid&31;
    __shared__ float red[4];
    float4 v = p4[tid];
    float m = fmaxf(fmaxf(v.x,v.y), fmaxf(v.z,v.w));
#pragma unroll
    for (int o=16;o;o>>=1) m = fmaxf(m, __shfl_xor_sync(0xffffffffu, m, o));
    if (l==0) red[w]=m;
    __syncthreads();
    m = fmaxf(fmaxf(red[0],red[1]), fmaxf(red[2],red[3]));
    __syncthreads();
    v.x = __expf(v.x-m); v.y = __expf(v.y-m); v.z = __expf(v.z-m); v.w = __expf(v.w-m);
    float s = v.x+v.y+v.z+v.w;
#pragma unroll
    for (int o=16;o;o>>=1) s += __shfl_xor_sync(0xffffffffu, s, o);
    if (l==0) red[w]=s;
    __syncthreads();
    s = red[0]+red[1]+red[2]+red[3];
    float inv = __frcp_rn(s);
    v.x*=inv; v.y*=inv; v.z*=inv; v.w*=inv;
    p4[tid] = v;
}

// layernorm over 768: FIRST => t = x + attnP + topo[b]; else t = x1 + ffn2
template<bool FIRST>
__global__ void ln_k(const float* __restrict__ a, const float* __restrict__ br,
                     const float* __restrict__ gamma, const float* __restrict__ beta,
                     float* __restrict__ out) {
    __shared__ float tv[D_];
    __shared__ float red[8];
    long r = blockIdx.x; int tid = threadIdx.x;
    float loc = 0.f;
    for (int d=tid; d<D_; d+=256) {
        float t = a[r*D_+d] + br[r*D_+d];
        if (FIRST) t += g_topo[(r>>9)*D_ + d];
        tv[d] = t; loc += t;
    }
    float mean = blockReduceSum256(loc, red) * (1.f/D_);
    float lv = 0.f;
    for (int d=tid; d<D_; d+=256) { float c = tv[d]-mean; lv += c*c; }
    float var = blockReduceSum256(lv, red) * (1.f/D_);
    float rs = rsqrtf(var + 1e-5f);
    for (int d=tid; d<D_; d+=256)
        out[r*D_+d] = (tv[d]-mean)*rs*gamma[d] + beta[d];
}

// ---------------- host-side symbol helpers ----------------
static float* symaddr(const void* sym) {
    void* p = nullptr;
    cudaGetSymbolAddress(&p, sym);
    return (float*)p;
}

extern "C" void kernel_launch(void* const* d_in, const int* in_sizes, int n_in,
                              void* d_out, int out_size) {
    const float* x        = (const float*)d_in[0];
    const int*   sidx     = (const int*)  d_in[1];
    const float* w1       = (const float*)d_in[2];
    const float* b1       = (const float*)d_in[3];
    const float* w2       = (const float*)d_in[4];
    const float* b2       = (const float*)d_in[5];
    const float* wd0      = (const float*)d_in[6];
    const float* bd0      = (const float*)d_in[7];
    // d_in[8], d_in[9] = wd1, bd1 (unused by reference)
    const float* in_w     = (const float*)d_in[10];
    const float* in_b     = (const float*)d_in[11];
    const float* out_w    = (const float*)d_in[12];
    const float* out_b    = (const float*)d_in[13];
    const float* topo_w   = (const float*)d_in[14];
    const float* topo_b   = (const float*)d_in[15];
    const float* gate     = (const float*)d_in[16];
    const float* ln1_g    = (const float*)d_in[17];
    const float* ln1_b    = (const float*)d_in[18];
    const float* ln2_g    = (const float*)d_in[19];
    const float* ln2_b    = (const float*)d_in[20];
    const float* ffn_w1   = (const float*)d_in[21];
    const float* ffn_b1   = (const float*)d_in[22];
    const float* ffn_w2   = (const float*)d_in[23];
    const float* ffn_b2   = (const float*)d_in[24];
    float* out = (float*)d_out;

    float* p_xnorm  = symaddr(g_xnorm);
    float* p_sbuf   = symaddr(g_sbuf);
    float* p_dist   = symaddr(g_dist);
    float* p_qkv    = symaddr(g_qkv);
    float* p_scores = symaddr(g_scores);
    float* p_attnO  = symaddr(g_attnO);
    float* p_attnP  = symaddr(g_attnP);
    float* p_x1     = symaddr(g_x1);
    float* p_ffnh   = symaddr(g_ffnh);
    float* p_ffn2   = symaddr(g_ffn2);

    // 1) per-row squared norms + sample gather + batch-stat init
    init_k<<<1,32>>>();
    xnorm_k<<<BS_,256>>>(x);
    gather_k<<<dim3(NS_,B_),192>>>(x, sidx);

    // 2) cdist: dist[b,s,n] = sqrt(|x|^2 + |s|^2 - 2 x.s)   (NT batched GEMM, EPI=3)
    gemm_k<128,128,8,8,8,true,3><<<dim3(1,4,B_),256>>>(
        x, p_sbuf, p_dist, nullptr,
        S_, NS_, D_, D_, D_, NS_,
        1, (long)S_*D_, 0, (long)NS_*D_, 0, (long)S_*NS_, 0,
        0.f, p_xnorm, sidx);

    // 3) top-16 per row + per-batch stats
    topk_stats_k<<<BS_/8,256>>>();

    // 4) stats -> landscape -> gated topo embedding
    mlp_topo_k<<<B_,256>>>(w1,b1,w2,b2,wd0,bd0,topo_w,topo_b,gate);

    // 5) QKV projection: [8192,768]@[768,2304]+bias
    gemm_k<128,128,8,8,8,false,0><<<dim3(3*D_/128, BS_/128, 1),256>>>(
        x, in_w, p_qkv, in_b,
        BS_, 3*D_, D_, D_, 3*D_, 3*D_,
        1, 0,0,0,0,0,0, 0.f, nullptr, nullptr);

    // 6) scores = Q @ K^T / 8  (batched over b,h; NT; EPI=2)
    gemm_k<128,128,8,8,8,true,2><<<dim3(S_/128, S_/128, B_*H_),256>>>(
        p_qkv, p_qkv + D_, p_scores, nullptr,
        S_, S_, HD_, 3*D_, 3*D_, S_,
        H_, (long)S_*3*D_, HD_, (long)S_*3*D_, HD_,
        (long)H_*S_*S_, (long)S_*S_,
        0.125f, nullptr, nullptr);

    // 7) softmax rows
    softmax_k<<<B_*H_*S_,128>>>();

    // 8) O = P @ V  (batched NN, BN=64)
    gemm_k<128,64,8,8,4,false,0><<<dim3(1, S_/128, B_*H_),256>>>(
        p_scores, p_qkv + 2*D_, p_attnO, nullptr,
        S_, HD_, S_, S_, 3*D_, D_,
        H_, (long)H_*S_*S_, (long)S_*S_, (long)S_*3*D_, HD_,
        (long)S_*D_, HD_,
        0.f, nullptr, nullptr);

    // 9) attn projection
    gemm_k<128,128,8,8,8,false,0><<<dim3(D_/128, BS_/128, 1),256>>>(
        p_attnO, out_w, p_attnP, out_b,
        BS_, D_, D_, D_, D_, D_,
        1, 0,0,0,0,0,0, 0.f, nullptr, nullptr);

    // 10) x1 = LN(x + attnP + gate*topo)
    ln_k<true><<<BS_,256>>>(x, p_attnP, ln1_g, ln1_b, p_x1);

    // 11) FFN1 with exact GELU
    gemm_k<128,128,8,8,8,false,1><<<dim3(2*D_/128, BS_/128, 1),256>>>(
        p_x1, ffn_w1, p_ffnh, ffn_b1,
        BS_, 2*D_, D_, D_, 2*D_, 2*D_,
        1, 0,0,0,0,0,0, 0.f, nullptr, nullptr);

    // 12) FFN2
    gemm_k<128,128,8,8,8,false,0><<<dim3(D_/128, BS_/128, 1),256>>>(
        p_ffnh, ffn_w2, p_ffn2, ffn_b2,
        BS_, D_, 2*D_, 2*D_, D_, D_,
        1, 0,0,0,0,0,0, 0.f, nullptr, nullptr);

    // 13) out = LN(x1 + ffn)
    ln_k<false><<<BS_,256>>>(p_x1, p_ffn2, ln2_g, ln2_b, out);
}